// round 11
// baseline (speedup 1.0000x reference)
#include <cuda_runtime.h>
#include <math.h>
#include <stdint.h>

#define M 5
#define NACC 20              // c[5] + packed upper Gram S[15]
#define NB1 888              // pass1 grid: 148 SMs * 3 CTAs * 2 waves
#define NB2 1184             // pass2 grid: 148 SMs * 4 CTAs * 2 waves
#define NTHREADS 256

__device__ float  g_y[M];
__device__ double g_partials[NB1 * NACC];

// ---- f32x2 packed helpers (sm_103a) ---------------------------------------
__device__ __forceinline__ uint64_t pk2(float a, float b) {
    uint64_t r;
    asm("mov.b64 %0, {%1, %2};" : "=l"(r) : "f"(a), "f"(b));
    return r;
}
__device__ __forceinline__ void upk2(float& a, float& b, uint64_t v) {
    asm("mov.b64 {%0, %1}, %2;" : "=f"(a), "=f"(b) : "l"(v));
}
__device__ __forceinline__ uint64_t fma2(uint64_t a, uint64_t b, uint64_t c) {
    uint64_t d;
    asm("fma.rn.f32x2 %0, %1, %2, %3;" : "=l"(d) : "l"(a), "l"(b), "l"(c));
    return d;
}
__device__ __forceinline__ uint64_t mul2(uint64_t a, uint64_t b) {
    uint64_t d;
    asm("mul.rn.f32x2 %0, %1, %2;" : "=l"(d) : "l"(a), "l"(b));
    return d;
}
__device__ __forceinline__ uint64_t add2(uint64_t a, uint64_t b) {
    uint64_t d;
    asm("add.rn.f32x2 %0, %1, %2;" : "=l"(d) : "l"(a), "l"(b));
    return d;
}
// packed quadratic form t^T Q t (upper-packed Q, off-diag pre-doubled)
__device__ __forceinline__ uint64_t sstQt2(const uint64_t* q2, const uint64_t* t2) {
    int qi = 0;
    uint64_t inner = mul2(q2[qi++], t2[0]);
#pragma unroll
    for (int k = 1; k < M; k++) inner = fma2(q2[qi++], t2[k], inner);
    uint64_t ss2 = mul2(inner, t2[0]);
#pragma unroll
    for (int j = 1; j < M; j++) {
        inner = mul2(q2[qi++], t2[j]);
#pragma unroll
        for (int k = j + 1; k < M; k++) inner = fma2(q2[qi++], t2[k], inner);
        ss2 = fma2(inner, t2[j], ss2);
    }
    return ss2;
}
// dv = 1/(sqrt(ss)+1e-8) ≈ r - 1e-8*r^2, r = rsqrt(ss)
__device__ __forceinline__ float dv_from_ss(float ss) {
    float r = rsqrtf(fmaxf(ss, 1e-16f));
    return fmaf(-1e-8f * r, r, r);
}
__device__ __forceinline__ uint64_t dv2_from_ss2(uint64_t ss2) {
    float sa, sb;
    upk2(sa, sb, ss2);
    return pk2(dv_from_ss(sa), dv_from_ss(sb));
}

// ---------------------------------------------------------------------------
// In-kernel prologue: Q = K^-1 (fp32 Gauss-Jordan, partial pivoting),
// packed-upper with off-diagonals pre-doubled. Deterministic; ~300 fp32 ops.
// WtW = V diag(1/s) V^T = K^-1 for full-rank PSD K (mask all ones).
// ---------------------------------------------------------------------------
__device__ void invert_K_packed(const float* __restrict__ K, float* __restrict__ qpk) {
    float A[M][M], Q[M][M];
#pragma unroll
    for (int i = 0; i < M; i++)
#pragma unroll
        for (int j = 0; j < M; j++) {
            A[i][j] = K[i * M + j];
            Q[i][j] = (i == j) ? 1.0f : 0.0f;
        }
    for (int col = 0; col < M; col++) {
        int piv = col;
        for (int r = col + 1; r < M; r++)
            if (fabsf(A[r][col]) > fabsf(A[piv][col])) piv = r;
        if (piv != col) {
            for (int c = 0; c < M; c++) {
                float t = A[col][c]; A[col][c] = A[piv][c]; A[piv][c] = t;
                t = Q[col][c]; Q[col][c] = Q[piv][c]; Q[piv][c] = t;
            }
        }
        float inv = 1.0f / A[col][col];
        for (int c = 0; c < M; c++) { A[col][c] *= inv; Q[col][c] *= inv; }
        for (int r = 0; r < M; r++) {
            if (r == col) continue;
            float f = A[r][col];
            for (int c = 0; c < M; c++) {
                A[r][c] = fmaf(-f, A[col][c], A[r][c]);
                Q[r][c] = fmaf(-f, Q[col][c], Q[r][c]);
            }
        }
    }
    int qi = 0;
#pragma unroll
    for (int j = 0; j < M; j++)
#pragma unroll
        for (int k = j; k < M; k++) {
            float q = 0.5f * (Q[j][k] + Q[k][j]);   // symmetrize
            qpk[qi++] = (k == j) ? q : 2.0f * q;
        }
}

// ---------------------------------------------------------------------------
// Kernel 1: streaming reduction — float4 loads, packed ss, scalar acc
//   (R6 proven hot loop; 3 CTAs/SM, 24 warps)
// ---------------------------------------------------------------------------
__global__ void __launch_bounds__(NTHREADS, 3)
kwng_pass1(const float* __restrict__ K, const float* __restrict__ T,
           const float* __restrict__ g, int D) {
    float qpk[15];
    invert_K_packed(K, qpk);
    uint64_t qpk2[15];
#pragma unroll
    for (int i = 0; i < 15; i++) qpk2[i] = pk2(qpk[i], qpk[i]);

    float acc[NACC];
#pragma unroll
    for (int a = 0; a < NACC; a++) acc[a] = 0.0f;

    const float4* __restrict__ T4 = (const float4*)T;
    const float4* __restrict__ g4 = (const float4*)g;
    const int n4 = D >> 2;

    for (int idx = blockIdx.x * blockDim.x + threadIdx.x; idx < n4;
         idx += gridDim.x * blockDim.x) {
        float4 tv[M];
#pragma unroll
        for (int j = 0; j < M; j++) tv[j] = T4[(size_t)j * n4 + idx];
        float4 gv = g4[idx];
        const float* tp = reinterpret_cast<const float*>(tv);
        const float* gp = reinterpret_cast<const float*>(&gv);
#pragma unroll
        for (int pr = 0; pr < 2; pr++) {
            uint64_t t2[M];
#pragma unroll
            for (int j = 0; j < M; j++)
                t2[j] = reinterpret_cast<const uint64_t*>(&tv[j])[pr];
            uint64_t ss2 = sstQt2(qpk2, t2);
            float s0, s1;
            upk2(s0, s1, ss2);
#pragma unroll
            for (int h = 0; h < 2; h++) {
                int lane = pr * 2 + h;
                float dv = dv_from_ss(h ? s1 : s0);
                float t[M];
#pragma unroll
                for (int j = 0; j < M; j++) t[j] = tp[j * 4 + lane];
                float dvg = dv * gp[lane];
#pragma unroll
                for (int j = 0; j < M; j++) acc[j] = fmaf(t[j], dvg, acc[j]);
                int ai = M;
#pragma unroll
                for (int j = 0; j < M; j++) {
                    float u = dv * t[j];
#pragma unroll
                    for (int k = j; k < M; k++) {
                        acc[ai] = fmaf(u, t[k], acc[ai]);
                        ai++;
                    }
                }
            }
        }
    }

    // deterministic block reduction
    __shared__ float sred[NTHREADS / 32][NACC];
    int lane = threadIdx.x & 31;
    int warp = threadIdx.x >> 5;
#pragma unroll
    for (int a = 0; a < NACC; a++) {
        float v = acc[a];
#pragma unroll
        for (int off = 16; off > 0; off >>= 1)
            v += __shfl_down_sync(0xffffffffu, v, off);
        if (lane == 0) sred[warp][a] = v;
    }
    __syncthreads();
    if (threadIdx.x < NACC) {
        double s = 0.0;
#pragma unroll
        for (int w = 0; w < NTHREADS / 32; w++) s += (double)sred[w][threadIdx.x];
        g_partials[(size_t)blockIdx.x * NACC + threadIdx.x] = s;
    }
}

// ---------------------------------------------------------------------------
// Kernel 2: reduce partials + fp32 tiny solve:  y = (S + eps*K)^-1 c
// ---------------------------------------------------------------------------
__global__ void kwng_reduce_solve(const float* __restrict__ K) {
    __shared__ float sacc[NACC];
    int a = threadIdx.x >> 5;
    int lane = threadIdx.x & 31;
    if (a < NACC) {
        double s = 0.0;
        for (int b = lane; b < NB1; b += 32)
            s += g_partials[(size_t)b * NACC + a];
#pragma unroll
        for (int off = 16; off > 0; off >>= 1)
            s += __shfl_down_sync(0xffffffffu, s, off);
        if (lane == 0) sacc[a] = (float)s;
    }
    __syncthreads();
    if (threadIdx.x == 0) {
        float c[M], A[M][M];
#pragma unroll
        for (int i = 0; i < M; i++) c[i] = sacc[i];
        int ai = M;
#pragma unroll
        for (int j = 0; j < M; j++)
#pragma unroll
            for (int k = j; k < M; k++) {
                float s = sacc[ai++];
                A[j][k] = s;
                A[k][j] = s;
            }
#pragma unroll
        for (int i = 0; i < M; i++)
#pragma unroll
            for (int j = 0; j < M; j++)
                A[i][j] = fmaf(1e-5f, K[i * M + j], A[i][j]);

        for (int col = 0; col < M; col++) {
            int piv = col;
            for (int r = col + 1; r < M; r++)
                if (fabsf(A[r][col]) > fabsf(A[piv][col])) piv = r;
            if (piv != col) {
                for (int cc = 0; cc < M; cc++) {
                    float t = A[col][cc]; A[col][cc] = A[piv][cc]; A[piv][cc] = t;
                }
                float tb = c[col]; c[col] = c[piv]; c[piv] = tb;
            }
            float inv = 1.0f / A[col][col];
            for (int r = col + 1; r < M; r++) {
                float f = A[r][col] * inv;
                for (int cc = col; cc < M; cc++)
                    A[r][cc] = fmaf(-f, A[col][cc], A[r][cc]);
                c[r] = fmaf(-f, c[col], c[r]);
            }
        }
        float y[M];
        for (int r = M - 1; r >= 0; r--) {
            float s = c[r];
            for (int cc = r + 1; cc < M; cc++) s = fmaf(-A[r][cc], y[cc], s);
            y[r] = s / A[r][r];
        }
#pragma unroll
        for (int i = 0; i < M; i++) g_y[i] = y[i];
    }
}

// ---------------------------------------------------------------------------
// Kernel 3: map pass (R6 proven form):  out = dv * (g + t.y) / eps
// ---------------------------------------------------------------------------
__global__ void __launch_bounds__(NTHREADS, 4)
kwng_pass2(const float* __restrict__ K, const float* __restrict__ T,
           const float* __restrict__ g, float* __restrict__ out, int D) {
    float qpk[15];
    invert_K_packed(K, qpk);
    uint64_t qpk2[15], y2[M];
#pragma unroll
    for (int i = 0; i < 15; i++) qpk2[i] = pk2(qpk[i], qpk[i]);
#pragma unroll
    for (int i = 0; i < M; i++) {
        float yv = g_y[i];
        y2[i] = pk2(yv, yv);
    }
    const uint64_t eps2 = pk2(1e5f, 1e5f);   // 1/eps

    const float4* __restrict__ T4 = (const float4*)T;
    const float4* __restrict__ g4 = (const float4*)g;
    float4* __restrict__ o4 = (float4*)out;
    const int n4 = D >> 2;

    for (int idx = blockIdx.x * blockDim.x + threadIdx.x; idx < n4;
         idx += gridDim.x * blockDim.x) {
        float4 tv[M];
#pragma unroll
        for (int j = 0; j < M; j++) tv[j] = T4[(size_t)j * n4 + idx];
        float4 gv = g4[idx];
        const uint64_t* gpp = reinterpret_cast<const uint64_t*>(&gv);
        float4 ov;
        uint64_t* opp = reinterpret_cast<uint64_t*>(&ov);
#pragma unroll
        for (int pr = 0; pr < 2; pr++) {
            uint64_t t2[M];
#pragma unroll
            for (int j = 0; j < M; j++)
                t2[j] = reinterpret_cast<const uint64_t*>(&tv[j])[pr];
            uint64_t ss2 = sstQt2(qpk2, t2);
            uint64_t dv2 = dv2_from_ss2(ss2);
            uint64_t cond2 = mul2(y2[0], t2[0]);
#pragma unroll
            for (int j = 1; j < M; j++) cond2 = fma2(y2[j], t2[j], cond2);
            uint64_t s2 = add2(gpp[pr], cond2);
            s2 = mul2(s2, eps2);
            opp[pr] = mul2(dv2, s2);
        }
        __stcs(&o4[idx], ov);
    }
}

// ---------------------------------------------------------------------------
extern "C" void kernel_launch(void* const* d_in, const int* in_sizes, int n_in,
                              void* d_out, int out_size) {
    const float* K = (const float*)d_in[0];   // [5,5]
    const float* T = (const float*)d_in[1];   // [5, D]
    const float* g = (const float*)d_in[2];   // [D]
    float* out = (float*)d_out;               // [D]
    int D = in_sizes[2];

    kwng_pass1<<<NB1, NTHREADS>>>(K, T, g, D);
    kwng_reduce_solve<<<1, NACC * 32>>>(K);
    kwng_pass2<<<NB2, NTHREADS>>>(K, T, g, out, D);
}

// round 12
// speedup vs baseline: 1.2349x; 1.2349x over previous
#include <cuda_runtime.h>
#include <math.h>
#include <stdint.h>

#define M 5
#define NACC 20              // c[5] + packed upper Gram S[15]
#define NB1 592              // pass1 grid: 148 SMs * 2 CTAs * 2 waves
#define NB2 1184             // pass2 grid: 148 SMs * 4 CTAs * 2 waves
#define NTHREADS 256

__device__ float  g_qpk[15];         // Q = K^-1 packed upper, off-diag doubled
__device__ float  g_y[M];
__device__ double g_partials[NB1 * NACC];

// ---- f32x2 packed helpers (sm_103a) ---------------------------------------
__device__ __forceinline__ uint64_t pk2(float a, float b) {
    uint64_t r;
    asm("mov.b64 %0, {%1, %2};" : "=l"(r) : "f"(a), "f"(b));
    return r;
}
__device__ __forceinline__ void upk2(float& a, float& b, uint64_t v) {
    asm("mov.b64 {%0, %1}, %2;" : "=f"(a), "=f"(b) : "l"(v));
}
__device__ __forceinline__ uint64_t fma2(uint64_t a, uint64_t b, uint64_t c) {
    uint64_t d;
    asm("fma.rn.f32x2 %0, %1, %2, %3;" : "=l"(d) : "l"(a), "l"(b), "l"(c));
    return d;
}
__device__ __forceinline__ uint64_t mul2(uint64_t a, uint64_t b) {
    uint64_t d;
    asm("mul.rn.f32x2 %0, %1, %2;" : "=l"(d) : "l"(a), "l"(b));
    return d;
}
__device__ __forceinline__ uint64_t add2(uint64_t a, uint64_t b) {
    uint64_t d;
    asm("add.rn.f32x2 %0, %1, %2;" : "=l"(d) : "l"(a), "l"(b));
    return d;
}
// packed quadratic form t^T Q t (upper-packed Q, off-diag pre-doubled)
__device__ __forceinline__ uint64_t sstQt2(const uint64_t* q2, const uint64_t* t2) {
    int qi = 0;
    uint64_t inner = mul2(q2[qi++], t2[0]);
#pragma unroll
    for (int k = 1; k < M; k++) inner = fma2(q2[qi++], t2[k], inner);
    uint64_t ss2 = mul2(inner, t2[0]);
#pragma unroll
    for (int j = 1; j < M; j++) {
        inner = mul2(q2[qi++], t2[j]);
#pragma unroll
        for (int k = j + 1; k < M; k++) inner = fma2(q2[qi++], t2[k], inner);
        ss2 = fma2(inner, t2[j], ss2);
    }
    return ss2;
}
// dv = 1/(sqrt(ss)+1e-8) ≈ r - 1e-8*r^2, r = rsqrt(ss)
__device__ __forceinline__ float dv_from_ss(float ss) {
    float r = rsqrtf(fmaxf(ss, 1e-16f));
    return fmaf(-1e-8f * r, r, r);
}
__device__ __forceinline__ uint64_t dv2_from_ss2(uint64_t ss2) {
    float sa, sb;
    upk2(sa, sb, ss2);
    return pk2(dv_from_ss(sa), dv_from_ss(sb));
}

// ---------------------------------------------------------------------------
// Kernel 1: Q = K^-1 via fp32 Gauss-Jordan, 1 thread (local-mem cost harmless
// here; inlining this into the big kernels forces local arrays — never again)
// ---------------------------------------------------------------------------
__global__ void kwng_setup(const float* __restrict__ K) {
    float A[M][M], Q[M][M];
#pragma unroll
    for (int i = 0; i < M; i++)
#pragma unroll
        for (int j = 0; j < M; j++) {
            A[i][j] = K[i * M + j];
            Q[i][j] = (i == j) ? 1.0f : 0.0f;
        }
    for (int col = 0; col < M; col++) {
        int piv = col;
        for (int r = col + 1; r < M; r++)
            if (fabsf(A[r][col]) > fabsf(A[piv][col])) piv = r;
        if (piv != col) {
            for (int c = 0; c < M; c++) {
                float t = A[col][c]; A[col][c] = A[piv][c]; A[piv][c] = t;
                t = Q[col][c]; Q[col][c] = Q[piv][c]; Q[piv][c] = t;
            }
        }
        float inv = 1.0f / A[col][col];
        for (int c = 0; c < M; c++) { A[col][c] *= inv; Q[col][c] *= inv; }
        for (int r = 0; r < M; r++) {
            if (r == col) continue;
            float f = A[r][col];
            for (int c = 0; c < M; c++) {
                A[r][c] = fmaf(-f, A[col][c], A[r][c]);
                Q[r][c] = fmaf(-f, Q[col][c], Q[r][c]);
            }
        }
    }
    int qi = 0;
#pragma unroll
    for (int j = 0; j < M; j++)
#pragma unroll
        for (int k = j; k < M; k++) {
            float q = 0.5f * (Q[j][k] + Q[k][j]);
            g_qpk[qi++] = (k == j) ? q : 2.0f * q;
        }
}

// one group's contribution (R6 proven inner math)
__device__ __forceinline__ void p1_group(const float4* tv, const float4& gv,
                                         const uint64_t* qpk2, float* acc) {
    const float* tp = reinterpret_cast<const float*>(tv);
    const float* gp = reinterpret_cast<const float*>(&gv);
#pragma unroll
    for (int pr = 0; pr < 2; pr++) {
        uint64_t t2[M];
#pragma unroll
        for (int j = 0; j < M; j++)
            t2[j] = reinterpret_cast<const uint64_t*>(&tv[j])[pr];
        uint64_t ss2 = sstQt2(qpk2, t2);
        float s0, s1;
        upk2(s0, s1, ss2);
#pragma unroll
        for (int h = 0; h < 2; h++) {
            int lane = pr * 2 + h;
            float dv = dv_from_ss(h ? s1 : s0);
            float t[M];
#pragma unroll
            for (int j = 0; j < M; j++) t[j] = tp[j * 4 + lane];
            float dvg = dv * gp[lane];
#pragma unroll
            for (int j = 0; j < M; j++) acc[j] = fmaf(t[j], dvg, acc[j]);
            int ai = M;
#pragma unroll
            for (int j = 0; j < M; j++) {
                float u = dv * t[j];
#pragma unroll
                for (int k = j; k < M; k++) {
                    acc[ai] = fmaf(u, t[k], acc[ai]);
                    ai++;
                }
            }
        }
    }
}

// ---------------------------------------------------------------------------
// Kernel 2: streaming reduction — manual 2x unroll: 12 LDG.128 in flight
//   per warp-iteration (2 CTAs/SM, 16 warps, ~98KB/SM in flight)
// ---------------------------------------------------------------------------
__global__ void __launch_bounds__(NTHREADS, 2)
kwng_pass1(const float* __restrict__ T, const float* __restrict__ g, int D) {
    uint64_t qpk2[15];
#pragma unroll
    for (int i = 0; i < 15; i++) {
        float q = g_qpk[i];
        qpk2[i] = pk2(q, q);
    }
    float acc[NACC];
#pragma unroll
    for (int a = 0; a < NACC; a++) acc[a] = 0.0f;

    const float4* __restrict__ T4 = (const float4*)T;
    const float4* __restrict__ g4 = (const float4*)g;
    const int n4 = D >> 2;
    const int stride = gridDim.x * blockDim.x;
    const float4 z4 = make_float4(0.0f, 0.0f, 0.0f, 0.0f);

    for (int idx = blockIdx.x * blockDim.x + threadIdx.x; idx < n4;
         idx += 2 * stride) {
        const int idxB = idx + stride;
        const bool hasB = idxB < n4;
        // front-batch all 12 loads
        float4 tvA[M], tvB[M], gvA, gvB;
#pragma unroll
        for (int j = 0; j < M; j++) tvA[j] = T4[(size_t)j * n4 + idx];
        gvA = g4[idx];
#pragma unroll
        for (int j = 0; j < M; j++)
            tvB[j] = hasB ? T4[(size_t)j * n4 + idxB] : z4;
        gvB = hasB ? g4[idxB] : z4;

        p1_group(tvA, gvA, qpk2, acc);
        p1_group(tvB, gvB, qpk2, acc);   // zero inputs -> zero contribution
    }

    // deterministic block reduction
    __shared__ float sred[NTHREADS / 32][NACC];
    int lane = threadIdx.x & 31;
    int warp = threadIdx.x >> 5;
#pragma unroll
    for (int a = 0; a < NACC; a++) {
        float v = acc[a];
#pragma unroll
        for (int off = 16; off > 0; off >>= 1)
            v += __shfl_down_sync(0xffffffffu, v, off);
        if (lane == 0) sred[warp][a] = v;
    }
    __syncthreads();
    if (threadIdx.x < NACC) {
        double s = 0.0;
#pragma unroll
        for (int w = 0; w < NTHREADS / 32; w++) s += (double)sred[w][threadIdx.x];
        g_partials[(size_t)blockIdx.x * NACC + threadIdx.x] = s;
    }
}

// ---------------------------------------------------------------------------
// Kernel 3: reduce partials + fp32 tiny solve:  y = (S + eps*K)^-1 c
// ---------------------------------------------------------------------------
__global__ void kwng_reduce_solve(const float* __restrict__ K) {
    __shared__ float sacc[NACC];
    int a = threadIdx.x >> 5;
    int lane = threadIdx.x & 31;
    if (a < NACC) {
        double s = 0.0;
        for (int b = lane; b < NB1; b += 32)
            s += g_partials[(size_t)b * NACC + a];
#pragma unroll
        for (int off = 16; off > 0; off >>= 1)
            s += __shfl_down_sync(0xffffffffu, s, off);
        if (lane == 0) sacc[a] = (float)s;
    }
    __syncthreads();
    if (threadIdx.x == 0) {
        float c[M], A[M][M];
#pragma unroll
        for (int i = 0; i < M; i++) c[i] = sacc[i];
        int ai = M;
#pragma unroll
        for (int j = 0; j < M; j++)
#pragma unroll
            for (int k = j; k < M; k++) {
                float s = sacc[ai++];
                A[j][k] = s;
                A[k][j] = s;
            }
#pragma unroll
        for (int i = 0; i < M; i++)
#pragma unroll
            for (int j = 0; j < M; j++)
                A[i][j] = fmaf(1e-5f, K[i * M + j], A[i][j]);

        for (int col = 0; col < M; col++) {
            int piv = col;
            for (int r = col + 1; r < M; r++)
                if (fabsf(A[r][col]) > fabsf(A[piv][col])) piv = r;
            if (piv != col) {
                for (int cc = 0; cc < M; cc++) {
                    float t = A[col][cc]; A[col][cc] = A[piv][cc]; A[piv][cc] = t;
                }
                float tb = c[col]; c[col] = c[piv]; c[piv] = tb;
            }
            float inv = 1.0f / A[col][col];
            for (int r = col + 1; r < M; r++) {
                float f = A[r][col] * inv;
                for (int cc = col; cc < M; cc++)
                    A[r][cc] = fmaf(-f, A[col][cc], A[r][cc]);
                c[r] = fmaf(-f, c[col], c[r]);
            }
        }
        float y[M];
        for (int r = M - 1; r >= 0; r--) {
            float s = c[r];
            for (int cc = r + 1; cc < M; cc++) s = fmaf(-A[r][cc], y[cc], s);
            y[r] = s / A[r][r];
        }
#pragma unroll
        for (int i = 0; i < M; i++) g_y[i] = y[i];
    }
}

// ---------------------------------------------------------------------------
// Kernel 4: map pass (R6 proven form):  out = dv * (g + t.y) / eps
// ---------------------------------------------------------------------------
__global__ void __launch_bounds__(NTHREADS, 4)
kwng_pass2(const float* __restrict__ T, const float* __restrict__ g,
           float* __restrict__ out, int D) {
    uint64_t qpk2[15], y2[M];
#pragma unroll
    for (int i = 0; i < 15; i++) {
        float q = g_qpk[i];
        qpk2[i] = pk2(q, q);
    }
#pragma unroll
    for (int i = 0; i < M; i++) {
        float yv = g_y[i];
        y2[i] = pk2(yv, yv);
    }
    const uint64_t eps2 = pk2(1e5f, 1e5f);   // 1/eps

    const float4* __restrict__ T4 = (const float4*)T;
    const float4* __restrict__ g4 = (const float4*)g;
    float4* __restrict__ o4 = (float4*)out;
    const int n4 = D >> 2;

    for (int idx = blockIdx.x * blockDim.x + threadIdx.x; idx < n4;
         idx += gridDim.x * blockDim.x) {
        float4 tv[M];
#pragma unroll
        for (int j = 0; j < M; j++) tv[j] = T4[(size_t)j * n4 + idx];
        float4 gv = g4[idx];
        const uint64_t* gpp = reinterpret_cast<const uint64_t*>(&gv);
        float4 ov;
        uint64_t* opp = reinterpret_cast<uint64_t*>(&ov);
#pragma unroll
        for (int pr = 0; pr < 2; pr++) {
            uint64_t t2[M];
#pragma unroll
            for (int j = 0; j < M; j++)
                t2[j] = reinterpret_cast<const uint64_t*>(&tv[j])[pr];
            uint64_t ss2 = sstQt2(qpk2, t2);
            uint64_t dv2 = dv2_from_ss2(ss2);
            uint64_t cond2 = mul2(y2[0], t2[0]);
#pragma unroll
            for (int j = 1; j < M; j++) cond2 = fma2(y2[j], t2[j], cond2);
            uint64_t s2 = add2(gpp[pr], cond2);
            s2 = mul2(s2, eps2);
            opp[pr] = mul2(dv2, s2);
        }
        __stcs(&o4[idx], ov);
    }
}

// ---------------------------------------------------------------------------
extern "C" void kernel_launch(void* const* d_in, const int* in_sizes, int n_in,
                              void* d_out, int out_size) {
    const float* K = (const float*)d_in[0];   // [5,5]
    const float* T = (const float*)d_in[1];   // [5, D]
    const float* g = (const float*)d_in[2];   // [D]
    float* out = (float*)d_out;               // [D]
    int D = in_sizes[2];

    kwng_setup<<<1, 1>>>(K);
    kwng_pass1<<<NB1, NTHREADS>>>(T, g, D);
    kwng_reduce_solve<<<1, NACC * 32>>>(K);
    kwng_pass2<<<NB2, NTHREADS>>>(T, g, out, D);
}

// round 13
// speedup vs baseline: 1.2721x; 1.0302x over previous
#include <cuda_runtime.h>
#include <math.h>
#include <stdint.h>

#define M 5
#define NACC 20              // c[5] + packed upper Gram S[15]
#define NB1 888              // pass1 grid: 148 SMs * 3 CTAs * 2 waves
#define NB2 1184             // pass2 grid: 148 SMs * 4 CTAs * 2 waves
#define NTHREADS 256

__device__ float  g_qpk[15];         // Q = K^-1 packed upper, off-diag doubled
__device__ float  g_y[M];
__device__ double g_partials[NB1 * NACC];

// ---- f32x2 packed helpers (sm_103a) ---------------------------------------
__device__ __forceinline__ uint64_t pk2(float a, float b) {
    uint64_t r;
    asm("mov.b64 %0, {%1, %2};" : "=l"(r) : "f"(a), "f"(b));
    return r;
}
__device__ __forceinline__ void upk2(float& a, float& b, uint64_t v) {
    asm("mov.b64 {%0, %1}, %2;" : "=f"(a), "=f"(b) : "l"(v));
}
__device__ __forceinline__ uint64_t fma2(uint64_t a, uint64_t b, uint64_t c) {
    uint64_t d;
    asm("fma.rn.f32x2 %0, %1, %2, %3;" : "=l"(d) : "l"(a), "l"(b), "l"(c));
    return d;
}
__device__ __forceinline__ uint64_t mul2(uint64_t a, uint64_t b) {
    uint64_t d;
    asm("mul.rn.f32x2 %0, %1, %2;" : "=l"(d) : "l"(a), "l"(b));
    return d;
}
__device__ __forceinline__ uint64_t add2(uint64_t a, uint64_t b) {
    uint64_t d;
    asm("add.rn.f32x2 %0, %1, %2;" : "=l"(d) : "l"(a), "l"(b));
    return d;
}
// packed quadratic form t^T Q t (upper-packed Q, off-diag pre-doubled)
__device__ __forceinline__ uint64_t sstQt2(const uint64_t* q2, const uint64_t* t2) {
    int qi = 0;
    uint64_t inner = mul2(q2[qi++], t2[0]);
#pragma unroll
    for (int k = 1; k < M; k++) inner = fma2(q2[qi++], t2[k], inner);
    uint64_t ss2 = mul2(inner, t2[0]);
#pragma unroll
    for (int j = 1; j < M; j++) {
        inner = mul2(q2[qi++], t2[j]);
#pragma unroll
        for (int k = j + 1; k < M; k++) inner = fma2(q2[qi++], t2[k], inner);
        ss2 = fma2(inner, t2[j], ss2);
    }
    return ss2;
}
// dv = 1/(sqrt(ss)+1e-8) ≈ r - 1e-8*r^2, r = rsqrt(ss)
__device__ __forceinline__ float dv_from_ss(float ss) {
    float r = rsqrtf(fmaxf(ss, 1e-16f));
    return fmaf(-1e-8f * r, r, r);
}
__device__ __forceinline__ uint64_t dv2_from_ss2(uint64_t ss2) {
    float sa, sb;
    upk2(sa, sb, ss2);
    return pk2(dv_from_ss(sa), dv_from_ss(sb));
}

// ---------------------------------------------------------------------------
// Kernel 1: Q = K^-1 via fp32 Gauss-Jordan with partial pivoting (1 thread).
// Local-memory cost is harmless in a 1-thread kernel; never inline into the
// streaming kernels (runtime pivots force local arrays there).
// ---------------------------------------------------------------------------
__global__ void kwng_setup(const float* __restrict__ K) {
    float A[M][M], Q[M][M];
#pragma unroll
    for (int i = 0; i < M; i++)
#pragma unroll
        for (int j = 0; j < M; j++) {
            A[i][j] = K[i * M + j];
            Q[i][j] = (i == j) ? 1.0f : 0.0f;
        }
    for (int col = 0; col < M; col++) {
        int piv = col;
        for (int r = col + 1; r < M; r++)
            if (fabsf(A[r][col]) > fabsf(A[piv][col])) piv = r;
        if (piv != col) {
            for (int c = 0; c < M; c++) {
                float t = A[col][c]; A[col][c] = A[piv][c]; A[piv][c] = t;
                t = Q[col][c]; Q[col][c] = Q[piv][c]; Q[piv][c] = t;
            }
        }
        float inv = 1.0f / A[col][col];
        for (int c = 0; c < M; c++) { A[col][c] *= inv; Q[col][c] *= inv; }
        for (int r = 0; r < M; r++) {
            if (r == col) continue;
            float f = A[r][col];
            for (int c = 0; c < M; c++) {
                A[r][c] = fmaf(-f, A[col][c], A[r][c]);
                Q[r][c] = fmaf(-f, Q[col][c], Q[r][c]);
            }
        }
    }
    int qi = 0;
#pragma unroll
    for (int j = 0; j < M; j++)
#pragma unroll
        for (int k = j; k < M; k++) {
            float q = 0.5f * (Q[j][k] + Q[k][j]);   // symmetrize
            g_qpk[qi++] = (k == j) ? q : 2.0f * q;
        }
}

// ---------------------------------------------------------------------------
// Kernel 2: streaming reduction — float4 __ldcg loads, packed ss, scalar acc
//   (proven best config: 3 CTAs/SM, 24 warps)
// ---------------------------------------------------------------------------
__global__ void __launch_bounds__(NTHREADS, 3)
kwng_pass1(const float* __restrict__ T, const float* __restrict__ g, int D) {
    uint64_t qpk2[15];
#pragma unroll
    for (int i = 0; i < 15; i++) {
        float q = g_qpk[i];
        qpk2[i] = pk2(q, q);
    }
    float acc[NACC];
#pragma unroll
    for (int a = 0; a < NACC; a++) acc[a] = 0.0f;

    const float4* __restrict__ T4 = (const float4*)T;
    const float4* __restrict__ g4 = (const float4*)g;
    const int n4 = D >> 2;

    for (int idx = blockIdx.x * blockDim.x + threadIdx.x; idx < n4;
         idx += gridDim.x * blockDim.x) {
        float4 tv[M];
#pragma unroll
        for (int j = 0; j < M; j++) tv[j] = __ldcg(&T4[(size_t)j * n4 + idx]);
        float4 gv = __ldcg(&g4[idx]);
        const float* tp = reinterpret_cast<const float*>(tv);
        const float* gp = reinterpret_cast<const float*>(&gv);
#pragma unroll
        for (int pr = 0; pr < 2; pr++) {
            uint64_t t2[M];
#pragma unroll
            for (int j = 0; j < M; j++)
                t2[j] = reinterpret_cast<const uint64_t*>(&tv[j])[pr];
            uint64_t ss2 = sstQt2(qpk2, t2);
            float s0, s1;
            upk2(s0, s1, ss2);
#pragma unroll
            for (int h = 0; h < 2; h++) {
                int lane = pr * 2 + h;
                float dv = dv_from_ss(h ? s1 : s0);
                float t[M];
#pragma unroll
                for (int j = 0; j < M; j++) t[j] = tp[j * 4 + lane];
                float dvg = dv * gp[lane];
#pragma unroll
                for (int j = 0; j < M; j++) acc[j] = fmaf(t[j], dvg, acc[j]);
                int ai = M;
#pragma unroll
                for (int j = 0; j < M; j++) {
                    float u = dv * t[j];
#pragma unroll
                    for (int k = j; k < M; k++) {
                        acc[ai] = fmaf(u, t[k], acc[ai]);
                        ai++;
                    }
                }
            }
        }
    }

    // deterministic block reduction
    __shared__ float sred[NTHREADS / 32][NACC];
    int lane = threadIdx.x & 31;
    int warp = threadIdx.x >> 5;
#pragma unroll
    for (int a = 0; a < NACC; a++) {
        float v = acc[a];
#pragma unroll
        for (int off = 16; off > 0; off >>= 1)
            v += __shfl_down_sync(0xffffffffu, v, off);
        if (lane == 0) sred[warp][a] = v;
    }
    __syncthreads();
    if (threadIdx.x < NACC) {
        double s = 0.0;
#pragma unroll
        for (int w = 0; w < NTHREADS / 32; w++) s += (double)sred[w][threadIdx.x];
        g_partials[(size_t)blockIdx.x * NACC + threadIdx.x] = s;
    }
}

// ---------------------------------------------------------------------------
// Kernel 3: reduce partials + fp32 tiny solve:  y = (S + eps*K)^-1 c
// ---------------------------------------------------------------------------
__global__ void kwng_reduce_solve(const float* __restrict__ K) {
    __shared__ float sacc[NACC];
    int a = threadIdx.x >> 5;
    int lane = threadIdx.x & 31;
    if (a < NACC) {
        double s = 0.0;
        for (int b = lane; b < NB1; b += 32)
            s += g_partials[(size_t)b * NACC + a];
#pragma unroll
        for (int off = 16; off > 0; off >>= 1)
            s += __shfl_down_sync(0xffffffffu, s, off);
        if (lane == 0) sacc[a] = (float)s;
    }
    __syncthreads();
    if (threadIdx.x == 0) {
        float c[M], A[M][M];
#pragma unroll
        for (int i = 0; i < M; i++) c[i] = sacc[i];
        int ai = M;
#pragma unroll
        for (int j = 0; j < M; j++)
#pragma unroll
            for (int k = j; k < M; k++) {
                float s = sacc[ai++];
                A[j][k] = s;
                A[k][j] = s;
            }
#pragma unroll
        for (int i = 0; i < M; i++)
#pragma unroll
            for (int j = 0; j < M; j++)
                A[i][j] = fmaf(1e-5f, K[i * M + j], A[i][j]);

        for (int col = 0; col < M; col++) {
            int piv = col;
            for (int r = col + 1; r < M; r++)
                if (fabsf(A[r][col]) > fabsf(A[piv][col])) piv = r;
            if (piv != col) {
                for (int cc = 0; cc < M; cc++) {
                    float t = A[col][cc]; A[col][cc] = A[piv][cc]; A[piv][cc] = t;
                }
                float tb = c[col]; c[col] = c[piv]; c[piv] = tb;
            }
            float inv = 1.0f / A[col][col];
            for (int r = col + 1; r < M; r++) {
                float f = A[r][col] * inv;
                for (int cc = col; cc < M; cc++)
                    A[r][cc] = fmaf(-f, A[col][cc], A[r][cc]);
                c[r] = fmaf(-f, c[col], c[r]);
            }
        }
        float y[M];
        for (int r = M - 1; r >= 0; r--) {
            float s = c[r];
            for (int cc = r + 1; cc < M; cc++) s = fmaf(-A[r][cc], y[cc], s);
            y[r] = s / A[r][r];
        }
#pragma unroll
        for (int i = 0; i < M; i++) g_y[i] = y[i];
    }
}

// ---------------------------------------------------------------------------
// Kernel 4: map pass — __ldcg loads, __stcs store:  out = dv*(g + t.y)/eps
// ---------------------------------------------------------------------------
__global__ void __launch_bounds__(NTHREADS, 4)
kwng_pass2(const float* __restrict__ T, const float* __restrict__ g,
           float* __restrict__ out, int D) {
    uint64_t qpk2[15], y2[M];
#pragma unroll
    for (int i = 0; i < 15; i++) {
        float q = g_qpk[i];
        qpk2[i] = pk2(q, q);
    }
#pragma unroll
    for (int i = 0; i < M; i++) {
        float yv = g_y[i];
        y2[i] = pk2(yv, yv);
    }
    const uint64_t eps2 = pk2(1e5f, 1e5f);   // 1/eps

    const float4* __restrict__ T4 = (const float4*)T;
    const float4* __restrict__ g4 = (const float4*)g;
    float4* __restrict__ o4 = (float4*)out;
    const int n4 = D >> 2;

    for (int idx = blockIdx.x * blockDim.x + threadIdx.x; idx < n4;
         idx += gridDim.x * blockDim.x) {
        float4 tv[M];
#pragma unroll
        for (int j = 0; j < M; j++) tv[j] = __ldcg(&T4[(size_t)j * n4 + idx]);
        float4 gv = __ldcg(&g4[idx]);
        const uint64_t* gpp = reinterpret_cast<const uint64_t*>(&gv);
        float4 ov;
        uint64_t* opp = reinterpret_cast<uint64_t*>(&ov);
#pragma unroll
        for (int pr = 0; pr < 2; pr++) {
            uint64_t t2[M];
#pragma unroll
            for (int j = 0; j < M; j++)
                t2[j] = reinterpret_cast<const uint64_t*>(&tv[j])[pr];
            uint64_t ss2 = sstQt2(qpk2, t2);
            uint64_t dv2 = dv2_from_ss2(ss2);
            uint64_t cond2 = mul2(y2[0], t2[0]);
#pragma unroll
            for (int j = 1; j < M; j++) cond2 = fma2(y2[j], t2[j], cond2);
            uint64_t s2 = add2(gpp[pr], cond2);
            s2 = mul2(s2, eps2);
            opp[pr] = mul2(dv2, s2);
        }
        __stcs(&o4[idx], ov);
    }
}

// ---------------------------------------------------------------------------
extern "C" void kernel_launch(void* const* d_in, const int* in_sizes, int n_in,
                              void* d_out, int out_size) {
    const float* K = (const float*)d_in[0];   // [5,5]
    const float* T = (const float*)d_in[1];   // [5, D]
    const float* g = (const float*)d_in[2];   // [D]
    float* out = (float*)d_out;               // [D]
    int D = in_sizes[2];

    kwng_setup<<<1, 1>>>(K);
    kwng_pass1<<<NB1, NTHREADS>>>(T, g, D);
    kwng_reduce_solve<<<1, NACC * 32>>>(K);
    kwng_pass2<<<NB2, NTHREADS>>>(T, g, out, D);
}